// round 15
// baseline (speedup 1.0000x reference)
#include <cuda_runtime.h>

// ContextEmbedding: per-token embedding assembly.
//   out[t, :] = special_emb(tok) + cls_branch(tok) + ctx_branch(tok)
// HBM-store-bound: 134MB out per launch. One warp per token.
// Streaming stores (.cs) keep the tiny read working set L2-resident.

#define D_MODEL 256
#define SPECIAL_OFFSET 68
#define NUM_SPECIAL 8
#define NUM_CONTEXT 16
#define LN_EPS 1e-5f

__device__ __forceinline__ void store_cs(float4* p, float4 v) {
    asm volatile("st.global.cs.v4.f32 [%0], {%1,%2,%3,%4};"
                 :: "l"(p), "f"(v.x), "f"(v.y), "f"(v.z), "f"(v.w) : "memory");
}

__global__ __launch_bounds__(256) void context_embedding_kernel(
    const int*   __restrict__ token_ids,
    const float* __restrict__ feat,          // [T, 16]
    const float* __restrict__ special_table, // [8, 256]
    const float* __restrict__ cls_w,         // [3, 256]
    const float* __restrict__ cls_b,
    const float* __restrict__ cls_g,
    const float* __restrict__ cls_beta,
    const float* __restrict__ ctx_w,         // [16, 256]
    const float* __restrict__ ctx_b,
    const float* __restrict__ ctx_g,
    const float* __restrict__ ctx_beta,
    float* __restrict__ out,                 // [T, 256]
    int n_tokens)
{
    const int warp = (blockIdx.x * blockDim.x + threadIdx.x) >> 5;
    const int lane = threadIdx.x & 31;
    if (warp >= n_tokens) return;

    const int tok = __ldg(token_ids + warp);
    float4* o = reinterpret_cast<float4*>(out + (size_t)warp * D_MODEL);
    const int sid = tok - SPECIAL_OFFSET;

    // Fast path 1: non-special token -> zeros (most tokens).
    if (sid < 0 || sid >= NUM_SPECIAL) {
        const float4 z = make_float4(0.f, 0.f, 0.f, 0.f);
        store_cs(o + lane,      z);
        store_cs(o + lane + 32, z);
        return;
    }

    // Embedding row (always added for special tokens).
    const float4* st = reinterpret_cast<const float4*>(special_table + sid * D_MODEL);
    float4 e0 = __ldg(st + lane);
    float4 e1 = __ldg(st + lane + 32);

    // Fast path 2: special but not CLS(0)/CONTEXT(1) -> embedding row only.
    if (sid > 1) {
        store_cs(o + lane,      e0);
        store_cs(o + lane + 32, e1);
        return;
    }

    // Branch parameters: sid==0 -> CLS (K=3), sid==1 -> CONTEXT (K=16).
    const bool  is_cls = (sid == 0);
    const int   K      = is_cls ? 3 : NUM_CONTEXT;
    const float* w     = is_cls ? cls_w    : ctx_w;     // [K, 256]
    const float* bvec  = is_cls ? cls_b    : ctx_b;
    const float* gvec  = is_cls ? cls_g    : ctx_g;
    const float* bevec = is_cls ? cls_beta : ctx_beta;
    const float* f     = feat + (size_t)warp * NUM_CONTEXT;

    // y = b + f @ w  (8 outputs per lane)
    float4 y0 = __ldg(reinterpret_cast<const float4*>(bvec) + lane);
    float4 y1 = __ldg(reinterpret_cast<const float4*>(bvec) + lane + 32);
    #pragma unroll 4
    for (int k = 0; k < K; ++k) {
        const float fk = __ldg(f + k);  // same addr across warp -> broadcast
        const float4 w0 = __ldg(reinterpret_cast<const float4*>(w + k * D_MODEL) + lane);
        const float4 w1 = __ldg(reinterpret_cast<const float4*>(w + k * D_MODEL) + lane + 32);
        y0.x = fmaf(fk, w0.x, y0.x); y0.y = fmaf(fk, w0.y, y0.y);
        y0.z = fmaf(fk, w0.z, y0.z); y0.w = fmaf(fk, w0.w, y0.w);
        y1.x = fmaf(fk, w1.x, y1.x); y1.y = fmaf(fk, w1.y, y1.y);
        y1.z = fmaf(fk, w1.z, y1.z); y1.w = fmaf(fk, w1.w, y1.w);
    }

    // LayerNorm over D=256 (warp reduction of sum and sumsq).
    float s  = y0.x + y0.y + y0.z + y0.w + y1.x + y1.y + y1.z + y1.w;
    float ss = y0.x*y0.x + y0.y*y0.y + y0.z*y0.z + y0.w*y0.w
             + y1.x*y1.x + y1.y*y1.y + y1.z*y1.z + y1.w*y1.w;
    #pragma unroll
    for (int off = 16; off > 0; off >>= 1) {
        s  += __shfl_xor_sync(0xffffffffu, s,  off);
        ss += __shfl_xor_sync(0xffffffffu, ss, off);
    }
    const float mean = s * (1.0f / D_MODEL);
    const float var  = fmaxf(ss * (1.0f / D_MODEL) - mean * mean, 0.0f);
    const float rstd = rsqrtf(var + LN_EPS);

    const float4 g0 = __ldg(reinterpret_cast<const float4*>(gvec) + lane);
    const float4 g1 = __ldg(reinterpret_cast<const float4*>(gvec) + lane + 32);
    const float4 be0 = __ldg(reinterpret_cast<const float4*>(bevec) + lane);
    const float4 be1 = __ldg(reinterpret_cast<const float4*>(bevec) + lane + 32);

    float4 r0, r1;
    r0.x = e0.x + fmaxf((y0.x - mean) * rstd * g0.x + be0.x, 0.0f);
    r0.y = e0.y + fmaxf((y0.y - mean) * rstd * g0.y + be0.y, 0.0f);
    r0.z = e0.z + fmaxf((y0.z - mean) * rstd * g0.z + be0.z, 0.0f);
    r0.w = e0.w + fmaxf((y0.w - mean) * rstd * g0.w + be0.w, 0.0f);
    r1.x = e1.x + fmaxf((y1.x - mean) * rstd * g1.x + be1.x, 0.0f);
    r1.y = e1.y + fmaxf((y1.y - mean) * rstd * g1.y + be1.y, 0.0f);
    r1.z = e1.z + fmaxf((y1.z - mean) * rstd * g1.z + be1.z, 0.0f);
    r1.w = e1.w + fmaxf((y1.w - mean) * rstd * g1.w + be1.w, 0.0f);

    store_cs(o + lane,      r0);
    store_cs(o + lane + 32, r1);
}

extern "C" void kernel_launch(void* const* d_in, const int* in_sizes, int n_in,
                              void* d_out, int out_size) {
    const int*   token_ids = (const int*)  d_in[0];
    const float* feat      = (const float*)d_in[1];
    const float* sp_table  = (const float*)d_in[2];
    const float* cls_w     = (const float*)d_in[3];
    const float* cls_b     = (const float*)d_in[4];
    const float* cls_g     = (const float*)d_in[5];
    const float* cls_beta  = (const float*)d_in[6];
    const float* ctx_w     = (const float*)d_in[7];
    const float* ctx_b     = (const float*)d_in[8];
    const float* ctx_g     = (const float*)d_in[9];
    const float* ctx_beta  = (const float*)d_in[10];
    float* out = (float*)d_out;

    int n_tokens = in_sizes[0];                 // B*S = 131072
    const int max_tokens = out_size / D_MODEL;
    if (n_tokens > max_tokens) n_tokens = max_tokens;

    const int WARPS_PER_BLOCK = 8;              // 256 threads
    const int blocks = (n_tokens + WARPS_PER_BLOCK - 1) / WARPS_PER_BLOCK;

    context_embedding_kernel<<<blocks, 256>>>(
        token_ids, feat, sp_table,
        cls_w, cls_b, cls_g, cls_beta,
        ctx_w, ctx_b, ctx_g, ctx_beta,
        out, n_tokens);
}